// round 2
// baseline (speedup 1.0000x reference)
#include <cuda_runtime.h>
#include <math.h>

// ---------------- constants ----------------
#define VOCAB 20000
#define Dd 100
#define Hh 100
#define N_NODE 256
#define Rr 8
#define Ss 52
#define SP 50
#define Ee 20000
#define NREV 2048

typedef unsigned long long u64;

__device__ __forceinline__ void ffma2(u64 &c, u64 a, u64 b) {
    asm("fma.rn.f32x2 %0, %1, %2, %0;" : "+l"(c) : "l"(a), "l"(b));
}
__device__ __forceinline__ float2 f2(u64 v) {
    float2 r; asm("mov.b64 {%0, %1}, %2;" : "=f"(r.x), "=f"(r.y) : "l"(v)); return r;
}

// ---------------- device scratch ----------------
__device__ __align__(16) float g_proj[VOCAB * 300];        // [v][k*100+h]
__device__ __align__(16) float g_w2t[Hh * Dd];             // [h][d]  transposed fc_w2_w
__device__ __align__(16) float g_P[2 * NREV * Dd];
__device__ __align__(16) float g_Q[2 * N_NODE * Dd];
__device__ __align__(16) float g_zw[2 * NREV];
__device__ __align__(16) float g_pc[2 * NREV];
__device__ __align__(16) float g_A[N_NODE * N_NODE * Rr];
__device__ __align__(16) float g_B[N_NODE * N_NODE * Rr];

// ---------------- K1: proj[v][k*100+h] = emb[v,:] . conv_w[h,0,k,:]  (f32x2 over d) ----
#define TVP 8
__global__ void proj_kernel(const float* __restrict__ emb, const float* __restrict__ convw,
                            const float* __restrict__ w2)
{
    if (blockIdx.x == VOCAB / TVP) {
        // tail block: transpose fc_w2_w -> g_w2t[h][d]
        for (int i = threadIdx.x; i < Dd * Hh; i += 160) {
            int d = i / Hh, h = i % Hh;
            g_w2t[h * Dd + d] = w2[i];
        }
        return;
    }
    __shared__ u64 esh[TVP][50];
    const int v0 = blockIdx.x * TVP;
    const int tid = threadIdx.x;

    for (int i = tid; i < TVP * 50; i += 160) {
        int v = i / 50, dp = i % 50;
        esh[v][dp] = reinterpret_cast<const u64*>(emb)[(v0 + v) * 50 + dp];
    }
    __syncthreads();
    if (tid >= 150) return;

    const int n0 = tid, n1 = tid + 150;
    const u64* w0p = reinterpret_cast<const u64*>(convw + (n0 % 100) * 300 + (n0 / 100) * 100);
    const u64* w1p = reinterpret_cast<const u64*>(convw + (n1 % 100) * 300 + (n1 / 100) * 100);

    u64 acc0[TVP], acc1[TVP];
#pragma unroll
    for (int v = 0; v < TVP; v++) { acc0[v] = 0ull; acc1[v] = 0ull; }

#pragma unroll 5
    for (int dp = 0; dp < 50; dp++) {
        u64 w0 = __ldg(w0p + dp);
        u64 w1 = __ldg(w1p + dp);
#pragma unroll
        for (int v = 0; v < TVP; v++) {
            u64 e = esh[v][dp];
            ffma2(acc0[v], e, w0);
            ffma2(acc1[v], e, w1);
        }
    }
#pragma unroll
    for (int v = 0; v < TVP; v++) {
        float2 a0 = f2(acc0[v]), a1 = f2(acc1[v]);
        g_proj[(v0 + v) * 300 + n0] = a0.x + a0.y;
        g_proj[(v0 + v) * 300 + n1] = a1.x + a1.y;
    }
}

// ---------------- K2: per-review fused kernel ----------------
// grid (2048, 2), block 192, dynamic smem.
// smem layout (floats):
//   rows   [52*301]   token proj rows, padded (301 mod 32 = 13 -> conflict-free)
//   cmax   [100]
//   Psh    [100]
//   zsh    [50]
//   cb     [100]
//   fw     [100]
//   tok    [52] (int)
#define ROWS_F (52 * 301)
#define RV_SMEM_F (ROWS_F + 100 + 100 + 50 + 100 + 100 + 52)

__global__ void review_kernel(const int* __restrict__ ur, const int* __restrict__ ir,
                              const float* __restrict__ convb,
                              const float* __restrict__ fcw, const float* __restrict__ fcb,
                              const float* __restrict__ w2b,
                              const float* __restrict__ hrw, const float* __restrict__ hcw,
                              float* __restrict__ out)
{
    extern __shared__ float sm[];
    float* rows = sm;
    float* cmax = sm + ROWS_F;
    float* Psh  = cmax + 100;
    float* zsh  = Psh + 100;
    float* cb   = zsh + 50;
    float* fw   = cb + 100;
    int*   tok  = (int*)(fw + 100);

    const int br  = blockIdx.y;
    const int idx = blockIdx.x;
    const int tid = threadIdx.x;
    const int* revs = br ? ir : ur;

    if (tid < Ss)  tok[tid] = revs[idx * Ss + tid];
    if (tid < Hh)  { cb[tid] = convb[tid]; fw[tid] = fcw[tid]; }
    __syncthreads();

    // stage 52 token rows (300 floats each) -> smem, coalesced streaming
#pragma unroll 4
    for (int t = 0; t < Ss; t++) {
        const float* src = g_proj + tok[t] * 300;
        float* dst = rows + t * 301;
        dst[tid] = src[tid];
        if (tid < 108) dst[tid + 192] = src[tid + 192];
    }
    __syncthreads();

    // rho/z on threads [0,50): recompute c(s,h) from smem rows
    if (tid < SP) {
        const int s = tid;
        const float* r0 = rows + s * 301;
        const float* r1 = rows + (s + 1) * 301 + 100;
        const float* r2 = rows + (s + 2) * 301 + 200;
        float x = fcb[0];
#pragma unroll 4
        for (int h = 0; h < Hh; h++) {
            float v = fmaxf(cb[h] + r0[h] + r1[h] + r2[h], 0.f);
            x += v * fw[h];
        }
        float rho = 1.f / (1.f + expf(-x));
        float z = rintf(rho);
        zsh[s] = z;
        out[2 * Ee + br * (NREV * SP) + idx * SP + s] = z;
    }
    // cmax on threads [64,164)
    if (tid >= 64 && tid < 64 + Hh) {
        const int h = tid - 64;
        const float b = cb[h];
        float m = 0.f;
#pragma unroll 2
        for (int s = 0; s < SP; s++) {
            float v = b + rows[s * 301 + h] + rows[(s + 1) * 301 + 100 + h]
                        + rows[(s + 2) * 301 + 200 + h];
            m = fmaxf(m, v);
        }
        cmax[h] = fmaxf(m, 0.f);
    }
    __syncthreads();

    // P[d] = w2b[d] + sum_h cmax[h] * w2t[h][d]   (coalesced over d)
    if (tid < Dd) {
        float p = w2b[tid];
#pragma unroll 4
        for (int h = 0; h < Hh; h++) p += cmax[h] * g_w2t[h * Dd + tid];
        Psh[tid] = p;
        g_P[(br * NREV + idx) * Dd + tid] = p;
    }
    // zw reduction on warp tid [160,192)
    if (tid >= 160) {
        const int l = tid - 160;
        float a = (l < SP) ? zsh[l] * hrw[br * SP + l] : 0.f;
        if (l + 32 < SP) a += zsh[l + 32] * hrw[br * SP + l + 32];
#pragma unroll
        for (int o = 16; o > 0; o >>= 1) a += __shfl_xor_sync(0xffffffffu, a, o);
        if (l == 0) g_zw[br * NREV + idx] = a;
    }
    __syncthreads();

    // pc reduction on warp 0
    if (tid < 32) {
        float a = 0.f;
#pragma unroll
        for (int j = 0; j < 4; j++) {
            int d = tid + 32 * j;
            if (d < Dd) a += Psh[d] * hcw[br * Dd + d];
        }
#pragma unroll
        for (int o = 16; o > 0; o >>= 1) a += __shfl_xor_sync(0xffffffffu, a, o);
        if (tid == 0) g_pc[br * NREV + idx] = a;
    }
}

// ---------------- K3: Q[node] = sum_r P[node,r,:]  (flat, coalesced) ----------------
__global__ void qsum_kernel()
{
    const int idx = blockIdx.x * 256 + threadIdx.x;
    if (idx >= 2 * N_NODE * Dd) return;
    const int node = idx / Dd;
    const int d = idx - node * Dd;
    float q = 0.f;
#pragma unroll
    for (int r = 0; r < Rr; r++) q += g_P[(node * Rr + r) * Dd + d];
    g_Q[idx] = q;
}

// ---------------- K4: pair scores, smem-staged + f32x2 ----------------
// grid (256, 2), block 128. Each thread: 2 other-nodes x 8 r.
// smem: Qs[256][102] (pad: 102*t mod 32 -> 6t, distinct per 16-lane phase) + Pa[800]
#define QS_PAD 102
#define PR_SMEM_F (N_NODE * QS_PAD + Rr * Dd)
__global__ void pair_kernel()
{
    extern __shared__ float sm[];
    float* Qs = sm;
    float* Pa = sm + N_NODE * QS_PAD;

    const int pb  = blockIdx.y;   // 0 -> A (u rows vs Q_i), 1 -> B
    const int a   = blockIdx.x;
    const int tid = threadIdx.x;
    const int wid = tid >> 5, lane = tid & 31;

    // stage opposite-side Q (coalesced)
    const float* qsrc = g_Q + (1 - pb) * N_NODE * Dd;
#pragma unroll 4
    for (int n = wid; n < N_NODE; n += 4) {
        const float* s = qsrc + n * Dd;
        float* d = Qs + n * QS_PAD;
        d[lane] = s[lane];
        d[lane + 32] = s[lane + 32];
        d[lane + 64] = s[lane + 64];
        if (lane < 4) d[lane + 96] = s[lane + 96];
    }
    // stage own 8 P rows
    const float* Pbase = g_P + (pb * NREV + a * Rr) * Dd;
    for (int i = tid; i < Rr * Dd; i += 128) Pa[i] = Pbase[i];
    __syncthreads();

    u64 acc[2][Rr];
#pragma unroll
    for (int j = 0; j < 2; j++)
#pragma unroll
        for (int r = 0; r < Rr; r++) acc[j][r] = 0ull;

    const u64* q0 = reinterpret_cast<const u64*>(Qs + tid * QS_PAD);
    const u64* q1 = reinterpret_cast<const u64*>(Qs + (tid + 128) * QS_PAD);
    const u64* Pu = reinterpret_cast<const u64*>(Pa);

#pragma unroll 5
    for (int dp = 0; dp < 50; dp++) {
        u64 a0 = q0[dp], a1 = q1[dp];
#pragma unroll
        for (int r = 0; r < Rr; r++) {
            u64 p = Pu[r * 50 + dp];
            ffma2(acc[0][r], a0, p);
            ffma2(acc[1][r], a1, p);
        }
    }

    float* base = (pb ? g_B : g_A) + a * N_NODE * Rr;
#pragma unroll
    for (int j = 0; j < 2; j++) {
        float v[Rr];
#pragma unroll
        for (int r = 0; r < Rr; r++) { float2 t = f2(acc[j][r]); v[r] = t.x + t.y; }
        float* dst = base + (tid + j * 128) * Rr;
        reinterpret_cast<float4*>(dst)[0] = make_float4(v[0], v[1], v[2], v[3]);
        reinterpret_cast<float4*>(dst)[1] = make_float4(v[4], v[5], v[6], v[7]);
    }
}

// ---------------- K5: per-edge predictions ----------------
__global__ void edge_kernel(const int* __restrict__ uid, const int* __restrict__ iid,
                            const float* __restrict__ ubias, const float* __restrict__ ibias,
                            const float* __restrict__ gbias, float* __restrict__ out)
{
    const int e = blockIdx.x * 256 + threadIdx.x;
    if (e >= Ee) return;
    const int u = uid[e], i = iid[e];

    const float4* A4 = reinterpret_cast<const float4*>(g_A + (u * N_NODE + i) * Rr);
    const float4* B4 = reinterpret_cast<const float4*>(g_B + (i * N_NODE + u) * Rr);
    float Av[Rr], Bv[Rr];
    *reinterpret_cast<float4*>(Av)     = A4[0];
    *reinterpret_cast<float4*>(Av + 4) = A4[1];
    *reinterpret_cast<float4*>(Bv)     = B4[0];
    *reinterpret_cast<float4*>(Bv + 4) = B4[1];

    const float* zwu = g_zw + u * Rr;
    const float* zwi = g_zw + NREV + i * Rr;
    const float* pcu = g_pc + u * Rr;
    const float* pci = g_pc + NREV + i * Rr;

    float pr = ubias[u] + ibias[i] + gbias[0];
    float pc = 0.f;
#pragma unroll
    for (int r = 0; r < Rr; r++) {
        float su = 1.f / (1.f + expf(-Av[r]));
        float sv = 1.f / (1.f + expf(-Bv[r]));
        pr += su * zwu[r] + sv * zwi[r];
        pc += su * pcu[r] + sv * pci[r];
    }
    out[e]      = pr;
    out[Ee + e] = pc;
}

// ---------------- launcher ----------------
extern "C" void kernel_launch(void* const* d_in, const int* in_sizes, int n_in,
                              void* d_out, int out_size)
{
    const int*   user_reviews = (const int*)  d_in[0];
    const int*   item_reviews = (const int*)  d_in[1];
    const int*   uid          = (const int*)  d_in[2];
    const int*   iid          = (const int*)  d_in[3];
    const float* emb_table    = (const float*)d_in[4];
    const float* conv_w       = (const float*)d_in[5];
    const float* conv_b       = (const float*)d_in[6];
    const float* fc_w_w       = (const float*)d_in[7];
    const float* fc_w_b       = (const float*)d_in[8];
    const float* fc_w2_w      = (const float*)d_in[9];
    const float* fc_w2_b      = (const float*)d_in[10];
    const float* h_r_w        = (const float*)d_in[11];
    const float* h_c_w        = (const float*)d_in[12];
    const float* user_bias    = (const float*)d_in[13];
    const float* item_bias    = (const float*)d_in[14];
    const float* global_bias  = (const float*)d_in[15];
    float* out = (float*)d_out;

    cudaFuncSetAttribute(review_kernel, cudaFuncAttributeMaxDynamicSharedMemorySize,
                         RV_SMEM_F * 4);
    cudaFuncSetAttribute(pair_kernel, cudaFuncAttributeMaxDynamicSharedMemorySize,
                         PR_SMEM_F * 4);

    proj_kernel<<<VOCAB / TVP + 1, 160>>>(emb_table, conv_w, fc_w2_w);
    review_kernel<<<dim3(NREV, 2), 192, RV_SMEM_F * 4>>>(user_reviews, item_reviews,
                                                         conv_b, fc_w_w, fc_w_b,
                                                         fc_w2_b, h_r_w, h_c_w, out);
    qsum_kernel<<<(2 * N_NODE * Dd + 255) / 256, 256>>>();
    pair_kernel<<<dim3(N_NODE, 2), 128, PR_SMEM_F * 4>>>();
    edge_kernel<<<(Ee + 255) / 256, 256>>>(uid, iid, user_bias, item_bias, global_bias, out);
}

// round 3
// speedup vs baseline: 2.2011x; 2.2011x over previous
#include <cuda_runtime.h>
#include <math.h>

// ---------------- constants ----------------
#define VOCAB 20000
#define Dd 100
#define Hh 100
#define N_NODE 256
#define Rr 8
#define Ss 52
#define SP 50
#define Ee 20000
#define NREV 2048

typedef unsigned long long u64;

__device__ __forceinline__ void ffma2(u64 &c, u64 a, u64 b) {
    asm("fma.rn.f32x2 %0, %1, %2, %0;" : "+l"(c) : "l"(a), "l"(b));
}
__device__ __forceinline__ float2 f2u(u64 v) {
    float2 r; asm("mov.b64 {%0, %1}, %2;" : "=f"(r.x), "=f"(r.y) : "l"(v)); return r;
}

// ---------------- device scratch ----------------
__device__ __align__(16) float g_proj[VOCAB * 300];     // [v][k*100+h]
__device__ __align__(16) float g_w2t[Hh * Dd];          // [h][d]
__device__ __align__(16) float g_P[2 * NREV * Dd];      // [(br*2048+node*8+r)][d]
__device__ __align__(16) float g_Qt[50 * 512 * 2];      // [d2][n] float2 pairs (d,d+1)
__device__ __align__(16) float g_zw[2 * NREV];
__device__ __align__(16) float g_pc[2 * NREV];
__device__ __align__(16) float g_A[N_NODE * N_NODE * Rr];
__device__ __align__(16) float g_B[N_NODE * N_NODE * Rr];

// ---------------- K1: proj (R1 register-tiled) + w2t tail block ----------------
#define TV 16
__global__ void proj_kernel(const float* __restrict__ emb, const float* __restrict__ convw,
                            const float* __restrict__ w2)
{
    if (blockIdx.x == VOCAB / TV) {
        for (int i = threadIdx.x; i < Dd * Hh; i += 160) {
            int d = i / Hh, h = i % Hh;
            g_w2t[h * Dd + d] = w2[i];
        }
        return;
    }
    __shared__ float4 esh[TV][25];
    const int v0 = blockIdx.x * TV;
    const int tid = threadIdx.x;

    for (int i = tid; i < TV * 25; i += 160) {
        int v = i / 25, d4 = i % 25;
        esh[v][d4] = reinterpret_cast<const float4*>(emb)[(v0 + v) * 25 + d4];
    }
    __syncthreads();

    const int n0 = tid;
    const int n1 = tid + 160;
    const bool has1 = (n1 < 300);
    const float4* w0p = reinterpret_cast<const float4*>(convw + (n0 % 100) * 300 + (n0 / 100) * 100);
    const float4* w1p = reinterpret_cast<const float4*>(convw + (has1 ? (n1 % 100) * 300 + (n1 / 100) * 100 : 0));

    float acc0[TV], acc1[TV];
#pragma unroll
    for (int v = 0; v < TV; v++) { acc0[v] = 0.f; acc1[v] = 0.f; }

    for (int d4 = 0; d4 < 25; d4++) {
        float4 w0 = w0p[d4];
        float4 w1 = has1 ? w1p[d4] : make_float4(0.f, 0.f, 0.f, 0.f);
#pragma unroll
        for (int v = 0; v < TV; v++) {
            float4 e = esh[v][d4];
            acc0[v] += e.x * w0.x + e.y * w0.y + e.z * w0.z + e.w * w0.w;
            acc1[v] += e.x * w1.x + e.y * w1.y + e.z * w1.z + e.w * w1.w;
        }
    }
#pragma unroll
    for (int v = 0; v < TV; v++) {
        g_proj[(v0 + v) * 300 + n0] = acc0[v];
        if (has1) g_proj[(v0 + v) * 300 + n1] = acc1[v];
    }
}

// ---------------- K2: per-review fused kernel (grid 4096, block 256) ----------------
__global__ void review_kernel(const int* __restrict__ ur, const int* __restrict__ ir,
                              const float* __restrict__ convb,
                              const float* __restrict__ fcw, const float* __restrict__ fcb,
                              const float* __restrict__ w2b,
                              const float* __restrict__ hrw, const float* __restrict__ hcw,
                              float* __restrict__ out)
{
    __shared__ __align__(16) float c_sh[SP * 104];   // rows padded to 26 float4
    __shared__ __align__(16) float cb[Hh], fw[Hh];
    __shared__ float zsh[SP], cmax[Hh], Psh[Hh];
    __shared__ int tok[Ss];

    const int bid = blockIdx.x;
    const int br  = bid >> 11;          // 0 user / 1 item
    const int idx = bid & 2047;
    const int tid = threadIdx.x;
    const int* revs = br ? ir : ur;

    if (tid < Ss)  tok[tid] = revs[idx * Ss + tid];
    if (tid >= 64 && tid < 64 + Hh) { int h = tid - 64; cb[h] = convb[h]; fw[h] = fcw[h]; }
    __syncthreads();

    // conv: c[s][h] = relu(cb[h] + proj[tok[s]][h] + proj[tok[s+1]][100+h] + proj[tok[s+2]][200+h])
    for (int i = tid; i < SP * 25; i += 256) {
        const int s = i / 25, h4 = i - s * 25;
        const float4 a = __ldg(reinterpret_cast<const float4*>(g_proj + tok[s]     * 300      ) + h4);
        const float4 b = __ldg(reinterpret_cast<const float4*>(g_proj + tok[s + 1] * 300 + 100) + h4);
        const float4 c = __ldg(reinterpret_cast<const float4*>(g_proj + tok[s + 2] * 300 + 200) + h4);
        const float4 bb = reinterpret_cast<const float4*>(cb)[h4];
        float4 v;
        v.x = fmaxf(bb.x + a.x + b.x + c.x, 0.f);
        v.y = fmaxf(bb.y + a.y + b.y + c.y, 0.f);
        v.z = fmaxf(bb.z + a.z + b.z + c.z, 0.f);
        v.w = fmaxf(bb.w + a.w + b.w + c.w, 0.f);
        reinterpret_cast<float4*>(c_sh + s * 104)[h4] = v;
    }
    __syncthreads();

    // rho -> z on warps 0-1
    if (tid < SP) {
        const float4* crow = reinterpret_cast<const float4*>(c_sh + tid * 104);
        float x = fcb[0];
#pragma unroll 5
        for (int j = 0; j < 25; j++) {
            float4 v = crow[j];
            float4 w = reinterpret_cast<const float4*>(fw)[j];
            x += v.x * w.x + v.y * w.y + v.z * w.z + v.w * w.w;
        }
        float rho = 1.f / (1.f + expf(-x));
        float z = rintf(rho);
        zsh[tid] = z;
        out[2 * Ee + bid * SP + tid] = z;
    }
    // cmax on warps 2-5
    if (tid >= 64 && tid < 64 + Hh) {
        const int h = tid - 64;
        float m = 0.f;
#pragma unroll 5
        for (int s = 0; s < SP; s++) m = fmaxf(m, c_sh[s * 104 + h]);
        cmax[h] = m;
    }
    __syncthreads();

    // P[d] (threads 0-99) — coalesced reads of transposed w2
    if (tid < Dd) {
        float p = w2b[tid];
#pragma unroll 4
        for (int h = 0; h < Hh; h++) p += cmax[h] * g_w2t[h * Dd + tid];
        Psh[tid] = p;
        g_P[bid * Dd + tid] = p;
    }
    // zw reduction on warp 6
    if (tid >= 192 && tid < 224) {
        const int l = tid - 192;
        float a = (l < SP) ? zsh[l] * hrw[br * SP + l] : 0.f;
        if (l + 32 < SP) a += zsh[l + 32] * hrw[br * SP + l + 32];
#pragma unroll
        for (int o = 16; o > 0; o >>= 1) a += __shfl_xor_sync(0xffffffffu, a, o);
        if (l == 0) g_zw[bid] = a;
    }
    __syncthreads();

    // pc reduction on warp 0
    if (tid < 32) {
        float a = 0.f;
#pragma unroll
        for (int j = 0; j < 4; j++) {
            int d = tid + 32 * j;
            if (d < Dd) a += Psh[d] * hcw[br * Dd + d];
        }
#pragma unroll
        for (int o = 16; o > 0; o >>= 1) a += __shfl_xor_sync(0xffffffffu, a, o);
        if (tid == 0) g_pc[bid] = a;
    }
}

// ---------------- K3: Qt2[d2][n] = (sum_r P[n,r,2d2], sum_r P[n,r,2d2+1]) ----------------
__global__ void qsum_kernel()
{
    const int idx = blockIdx.x * 256 + threadIdx.x;   // d2*512 + n
    if (idx >= 50 * 512) return;
    const int d2 = idx >> 9;
    const int n  = idx & 511;
    float qx = 0.f, qy = 0.f;
    const float* base = g_P + n * (Rr * Dd) + 2 * d2;
#pragma unroll
    for (int r = 0; r < Rr; r++) {
        float2 p = *reinterpret_cast<const float2*>(base + r * Dd);
        qx += p.x; qy += p.y;
    }
    reinterpret_cast<float2*>(g_Qt)[idx] = make_float2(qx, qy);
}

// ---------------- K4: pair scores — coalesced Qt + smem P broadcast + f32x2 ----------------
// grid (256, 2), block 256. thread tid = other node.
__global__ void pair_kernel()
{
    __shared__ __align__(16) float Pa[Rr * Dd];       // 3.2KB -> high occupancy

    const int pb  = blockIdx.y;    // 0 -> A (P_u vs Q_i), 1 -> B
    const int a   = blockIdx.x;
    const int tid = threadIdx.x;

    const float* Pbase = g_P + (pb * NREV + a * Rr) * Dd;
    for (int i = tid; i < Rr * Dd; i += 256) Pa[i] = Pbase[i];
    __syncthreads();

    const int off = (1 - pb) * N_NODE;
    const u64* qcol = reinterpret_cast<const u64*>(g_Qt) + off + tid;
    const u64* Pu   = reinterpret_cast<const u64*>(Pa);

    u64 acc[Rr];
#pragma unroll
    for (int r = 0; r < Rr; r++) acc[r] = 0ull;

#pragma unroll 5
    for (int d2 = 0; d2 < 50; d2++) {
        u64 q = __ldg(qcol + d2 * 512);               // coalesced LDG.64
#pragma unroll
        for (int r = 0; r < Rr; r++) ffma2(acc[r], q, Pu[r * 50 + d2]);   // LDS broadcast
    }

    float v[Rr];
#pragma unroll
    for (int r = 0; r < Rr; r++) { float2 t = f2u(acc[r]); v[r] = t.x + t.y; }
    float* dst = (pb ? g_B : g_A) + (a * N_NODE + tid) * Rr;
    reinterpret_cast<float4*>(dst)[0] = make_float4(v[0], v[1], v[2], v[3]);
    reinterpret_cast<float4*>(dst)[1] = make_float4(v[4], v[5], v[6], v[7]);
}

// ---------------- K5: per-edge predictions ----------------
__global__ void edge_kernel(const int* __restrict__ uid, const int* __restrict__ iid,
                            const float* __restrict__ ubias, const float* __restrict__ ibias,
                            const float* __restrict__ gbias, float* __restrict__ out)
{
    const int e = blockIdx.x * 256 + threadIdx.x;
    if (e >= Ee) return;
    const int u = uid[e], i = iid[e];

    const float4* A4 = reinterpret_cast<const float4*>(g_A + (u * N_NODE + i) * Rr);
    const float4* B4 = reinterpret_cast<const float4*>(g_B + (i * N_NODE + u) * Rr);
    float Av[Rr], Bv[Rr];
    *reinterpret_cast<float4*>(Av)     = A4[0];
    *reinterpret_cast<float4*>(Av + 4) = A4[1];
    *reinterpret_cast<float4*>(Bv)     = B4[0];
    *reinterpret_cast<float4*>(Bv + 4) = B4[1];

    const float* zwu = g_zw + u * Rr;
    const float* zwi = g_zw + NREV + i * Rr;
    const float* pcu = g_pc + u * Rr;
    const float* pci = g_pc + NREV + i * Rr;

    float pr = ubias[u] + ibias[i] + gbias[0];
    float pc = 0.f;
#pragma unroll
    for (int r = 0; r < Rr; r++) {
        float su = 1.f / (1.f + expf(-Av[r]));
        float sv = 1.f / (1.f + expf(-Bv[r]));
        pr += su * zwu[r] + sv * zwi[r];
        pc += su * pcu[r] + sv * pci[r];
    }
    out[e]      = pr;
    out[Ee + e] = pc;
}

// ---------------- launcher ----------------
extern "C" void kernel_launch(void* const* d_in, const int* in_sizes, int n_in,
                              void* d_out, int out_size)
{
    const int*   user_reviews = (const int*)  d_in[0];
    const int*   item_reviews = (const int*)  d_in[1];
    const int*   uid          = (const int*)  d_in[2];
    const int*   iid          = (const int*)  d_in[3];
    const float* emb_table    = (const float*)d_in[4];
    const float* conv_w       = (const float*)d_in[5];
    const float* conv_b       = (const float*)d_in[6];
    const float* fc_w_w       = (const float*)d_in[7];
    const float* fc_w_b       = (const float*)d_in[8];
    const float* fc_w2_w      = (const float*)d_in[9];
    const float* fc_w2_b      = (const float*)d_in[10];
    const float* h_r_w        = (const float*)d_in[11];
    const float* h_c_w        = (const float*)d_in[12];
    const float* user_bias    = (const float*)d_in[13];
    const float* item_bias    = (const float*)d_in[14];
    const float* global_bias  = (const float*)d_in[15];
    float* out = (float*)d_out;

    proj_kernel<<<VOCAB / TV + 1, 160>>>(emb_table, conv_w, fc_w2_w);
    review_kernel<<<2 * NREV, 256>>>(user_reviews, item_reviews,
                                     conv_b, fc_w_w, fc_w_b,
                                     fc_w2_b, h_r_w, h_c_w, out);
    qsum_kernel<<<(50 * 512 + 255) / 256, 256>>>();
    pair_kernel<<<dim3(N_NODE, 2), 256>>>();
    edge_kernel<<<(Ee + 255) / 256, 256>>>(uid, iid, user_bias, item_bias, global_bias, out);
}

// round 4
// speedup vs baseline: 2.2832x; 1.0373x over previous
#include <cuda_runtime.h>
#include <math.h>

// ---------------- constants ----------------
#define VOCAB 20000
#define Dd 100
#define Hh 100
#define N_NODE 256
#define Rr 8
#define Ss 52
#define SP 50
#define Ee 20000
#define NREV 2048

typedef unsigned long long u64;

__device__ __forceinline__ void ffma2(u64 &c, u64 a, u64 b) {
    asm("fma.rn.f32x2 %0, %1, %2, %0;" : "+l"(c) : "l"(a), "l"(b));
}
__device__ __forceinline__ float2 f2u(u64 v) {
    float2 r; asm("mov.b64 {%0, %1}, %2;" : "=f"(r.x), "=f"(r.y) : "l"(v)); return r;
}

union V4 { float4 f; u64 u[2]; };

// ---------------- device scratch ----------------
__device__ __align__(16) float g_proj[VOCAB * 300];     // [v][k*100+h]
__device__ __align__(16) float g_w2t[Hh * Dd];          // [h][d]
__device__ __align__(16) float g_P[2 * NREV * Dd];      // [(br*2048+node*8+r)][d]
__device__ __align__(16) float g_Qt[50 * 512 * 2];      // [d2][n] float2 pairs
__device__ __align__(16) float g_zw[2 * NREV];
__device__ __align__(16) float g_pc[2 * NREV];
__device__ __align__(16) float g_A[N_NODE * N_NODE * Rr];
__device__ __align__(16) float g_B[N_NODE * N_NODE * Rr];

// ---------------- K1: proj via f32x2, register-tiled ----------------
#define TVP 8
__global__ void proj_kernel(const float* __restrict__ emb, const float* __restrict__ convw,
                            const float* __restrict__ w2)
{
    if (blockIdx.x == VOCAB / TVP) {
        for (int i = threadIdx.x; i < Dd * Hh; i += 160) {
            int d = i / Hh, h = i % Hh;
            g_w2t[h * Dd + d] = w2[i];
        }
        return;
    }
    __shared__ __align__(16) float4 esh[TVP][25];
    const int v0 = blockIdx.x * TVP;
    const int tid = threadIdx.x;

    for (int i = tid; i < TVP * 25; i += 160) {
        int v = i / 25, d4 = i % 25;
        esh[v][d4] = reinterpret_cast<const float4*>(emb)[(v0 + v) * 25 + d4];
    }
    __syncthreads();
    if (tid >= 150) return;

    const int n0 = tid, n1 = tid + 150;
    const float4* w0p = reinterpret_cast<const float4*>(convw + (n0 % 100) * 300 + (n0 / 100) * 100);
    const float4* w1p = reinterpret_cast<const float4*>(convw + (n1 % 100) * 300 + (n1 / 100) * 100);

    u64 acc0[TVP], acc1[TVP];
#pragma unroll
    for (int v = 0; v < TVP; v++) { acc0[v] = 0ull; acc1[v] = 0ull; }

#pragma unroll 5
    for (int j = 0; j < 25; j++) {
        V4 w0, w1;
        w0.f = __ldg(w0p + j);
        w1.f = __ldg(w1p + j);
#pragma unroll
        for (int v = 0; v < TVP; v++) {
            V4 e; e.f = esh[v][j];
            ffma2(acc0[v], e.u[0], w0.u[0]);
            ffma2(acc0[v], e.u[1], w0.u[1]);
            ffma2(acc1[v], e.u[0], w1.u[0]);
            ffma2(acc1[v], e.u[1], w1.u[1]);
        }
    }
#pragma unroll
    for (int v = 0; v < TVP; v++) {
        float2 a0 = f2u(acc0[v]), a1 = f2u(acc1[v]);
        g_proj[(v0 + v) * 300 + n0] = a0.x + a0.y;
        g_proj[(v0 + v) * 300 + n1] = a1.x + a1.y;
    }
}

// ---------------- K2: per-review fused kernel (unchanged from R3) ----------------
__global__ void review_kernel(const int* __restrict__ ur, const int* __restrict__ ir,
                              const float* __restrict__ convb,
                              const float* __restrict__ fcw, const float* __restrict__ fcb,
                              const float* __restrict__ w2b,
                              const float* __restrict__ hrw, const float* __restrict__ hcw,
                              float* __restrict__ out)
{
    __shared__ __align__(16) float c_sh[SP * 104];
    __shared__ __align__(16) float cb[Hh], fw[Hh];
    __shared__ float zsh[SP], cmax[Hh], Psh[Hh];
    __shared__ int tok[Ss];

    const int bid = blockIdx.x;
    const int br  = bid >> 11;
    const int idx = bid & 2047;
    const int tid = threadIdx.x;
    const int* revs = br ? ir : ur;

    if (tid < Ss)  tok[tid] = revs[idx * Ss + tid];
    if (tid >= 64 && tid < 64 + Hh) { int h = tid - 64; cb[h] = convb[h]; fw[h] = fcw[h]; }
    __syncthreads();

    for (int i = tid; i < SP * 25; i += 256) {
        const int s = i / 25, h4 = i - s * 25;
        const float4 a = __ldg(reinterpret_cast<const float4*>(g_proj + tok[s]     * 300      ) + h4);
        const float4 b = __ldg(reinterpret_cast<const float4*>(g_proj + tok[s + 1] * 300 + 100) + h4);
        const float4 c = __ldg(reinterpret_cast<const float4*>(g_proj + tok[s + 2] * 300 + 200) + h4);
        const float4 bb = reinterpret_cast<const float4*>(cb)[h4];
        float4 v;
        v.x = fmaxf(bb.x + a.x + b.x + c.x, 0.f);
        v.y = fmaxf(bb.y + a.y + b.y + c.y, 0.f);
        v.z = fmaxf(bb.z + a.z + b.z + c.z, 0.f);
        v.w = fmaxf(bb.w + a.w + b.w + c.w, 0.f);
        reinterpret_cast<float4*>(c_sh + s * 104)[h4] = v;
    }
    __syncthreads();

    if (tid < SP) {
        const float4* crow = reinterpret_cast<const float4*>(c_sh + tid * 104);
        float x = fcb[0];
#pragma unroll 5
        for (int j = 0; j < 25; j++) {
            float4 v = crow[j];
            float4 w = reinterpret_cast<const float4*>(fw)[j];
            x += v.x * w.x + v.y * w.y + v.z * w.z + v.w * w.w;
        }
        float rho = 1.f / (1.f + expf(-x));
        float z = rintf(rho);
        zsh[tid] = z;
        out[2 * Ee + bid * SP + tid] = z;
    }
    if (tid >= 64 && tid < 64 + Hh) {
        const int h = tid - 64;
        float m = 0.f;
#pragma unroll 5
        for (int s = 0; s < SP; s++) m = fmaxf(m, c_sh[s * 104 + h]);
        cmax[h] = m;
    }
    __syncthreads();

    if (tid < Dd) {
        float p = w2b[tid];
#pragma unroll 4
        for (int h = 0; h < Hh; h++) p += cmax[h] * g_w2t[h * Dd + tid];
        Psh[tid] = p;
        g_P[bid * Dd + tid] = p;
    }
    if (tid >= 192 && tid < 224) {
        const int l = tid - 192;
        float a = (l < SP) ? zsh[l] * hrw[br * SP + l] : 0.f;
        if (l + 32 < SP) a += zsh[l + 32] * hrw[br * SP + l + 32];
#pragma unroll
        for (int o = 16; o > 0; o >>= 1) a += __shfl_xor_sync(0xffffffffu, a, o);
        if (l == 0) g_zw[bid] = a;
    }
    __syncthreads();

    if (tid < 32) {
        float a = 0.f;
#pragma unroll
        for (int j = 0; j < 4; j++) {
            int d = tid + 32 * j;
            if (d < Dd) a += Psh[d] * hcw[br * Dd + d];
        }
#pragma unroll
        for (int o = 16; o > 0; o >>= 1) a += __shfl_xor_sync(0xffffffffu, a, o);
        if (tid == 0) g_pc[bid] = a;
    }
}

// ---------------- K3: Qt2[d2][n] = sum_r P[n,r,(2d2,2d2+1)] ----------------
__global__ void qsum_kernel()
{
    const int idx = blockIdx.x * 256 + threadIdx.x;   // d2*512 + n
    if (idx >= 50 * 512) return;
    const int d2 = idx >> 9;
    const int n  = idx & 511;
    float qx = 0.f, qy = 0.f;
    const float* base = g_P + n * (Rr * Dd) + 2 * d2;
#pragma unroll
    for (int r = 0; r < Rr; r++) {
        float2 p = *reinterpret_cast<const float2*>(base + r * Dd);
        qx += p.x; qy += p.y;
    }
    reinterpret_cast<float2*>(g_Qt)[idx] = make_float2(qx, qy);
}

// ---------------- K4: pair scores — coalesced Qt + LDS.128 transposed P + full unroll --
// grid (256, 2), block 256. thread tid = other node.
__global__ void pair_kernel()
{
    __shared__ __align__(16) float Pt[50 * 16];   // [d2][r*2 + (d&1)]  3.2KB

    const int pb  = blockIdx.y;    // 0 -> A (P_u vs Q_i), 1 -> B
    const int a   = blockIdx.x;
    const int tid = threadIdx.x;

    const float* Pbase = g_P + (pb * NREV + a * Rr) * Dd;
    for (int i = tid; i < Rr * Dd; i += 256) {
        int r = i / Dd, d = i - r * Dd;
        Pt[(d >> 1) * 16 + r * 2 + (d & 1)] = Pbase[i];
    }
    __syncthreads();

    const int off = (1 - pb) * N_NODE;
    const u64* qcol = reinterpret_cast<const u64*>(g_Qt) + off + tid;

    u64 acc[Rr];
#pragma unroll
    for (int r = 0; r < Rr; r++) acc[r] = 0ull;

#pragma unroll
    for (int d2 = 0; d2 < 50; d2++) {
        u64 q = __ldg(qcol + d2 * 512);                 // coalesced LDG.64
        const float4* row = reinterpret_cast<const float4*>(Pt + d2 * 16);
        V4 p0, p1, p2, p3;                              // 4x LDS.128 broadcast
        p0.f = row[0]; p1.f = row[1]; p2.f = row[2]; p3.f = row[3];
        ffma2(acc[0], q, p0.u[0]);
        ffma2(acc[1], q, p0.u[1]);
        ffma2(acc[2], q, p1.u[0]);
        ffma2(acc[3], q, p1.u[1]);
        ffma2(acc[4], q, p2.u[0]);
        ffma2(acc[5], q, p2.u[1]);
        ffma2(acc[6], q, p3.u[0]);
        ffma2(acc[7], q, p3.u[1]);
    }

    float v[Rr];
#pragma unroll
    for (int r = 0; r < Rr; r++) { float2 t = f2u(acc[r]); v[r] = t.x + t.y; }
    float* dst = (pb ? g_B : g_A) + (a * N_NODE + tid) * Rr;
    reinterpret_cast<float4*>(dst)[0] = make_float4(v[0], v[1], v[2], v[3]);
    reinterpret_cast<float4*>(dst)[1] = make_float4(v[4], v[5], v[6], v[7]);
}

// ---------------- K5: per-edge predictions ----------------
__global__ void edge_kernel(const int* __restrict__ uid, const int* __restrict__ iid,
                            const float* __restrict__ ubias, const float* __restrict__ ibias,
                            const float* __restrict__ gbias, float* __restrict__ out)
{
    const int e = blockIdx.x * 256 + threadIdx.x;
    if (e >= Ee) return;
    const int u = uid[e], i = iid[e];

    const float4* A4 = reinterpret_cast<const float4*>(g_A + (u * N_NODE + i) * Rr);
    const float4* B4 = reinterpret_cast<const float4*>(g_B + (i * N_NODE + u) * Rr);
    float Av[Rr], Bv[Rr];
    *reinterpret_cast<float4*>(Av)     = A4[0];
    *reinterpret_cast<float4*>(Av + 4) = A4[1];
    *reinterpret_cast<float4*>(Bv)     = B4[0];
    *reinterpret_cast<float4*>(Bv + 4) = B4[1];

    const float* zwu = g_zw + u * Rr;
    const float* zwi = g_zw + NREV + i * Rr;
    const float* pcu = g_pc + u * Rr;
    const float* pci = g_pc + NREV + i * Rr;

    float pr = ubias[u] + ibias[i] + gbias[0];
    float pc = 0.f;
#pragma unroll
    for (int r = 0; r < Rr; r++) {
        float su = 1.f / (1.f + expf(-Av[r]));
        float sv = 1.f / (1.f + expf(-Bv[r]));
        pr += su * zwu[r] + sv * zwi[r];
        pc += su * pcu[r] + sv * pci[r];
    }
    out[e]      = pr;
    out[Ee + e] = pc;
}

// ---------------- launcher ----------------
extern "C" void kernel_launch(void* const* d_in, const int* in_sizes, int n_in,
                              void* d_out, int out_size)
{
    const int*   user_reviews = (const int*)  d_in[0];
    const int*   item_reviews = (const int*)  d_in[1];
    const int*   uid          = (const int*)  d_in[2];
    const int*   iid          = (const int*)  d_in[3];
    const float* emb_table    = (const float*)d_in[4];
    const float* conv_w       = (const float*)d_in[5];
    const float* conv_b       = (const float*)d_in[6];
    const float* fc_w_w       = (const float*)d_in[7];
    const float* fc_w_b       = (const float*)d_in[8];
    const float* fc_w2_w      = (const float*)d_in[9];
    const float* fc_w2_b      = (const float*)d_in[10];
    const float* h_r_w        = (const float*)d_in[11];
    const float* h_c_w        = (const float*)d_in[12];
    const float* user_bias    = (const float*)d_in[13];
    const float* item_bias    = (const float*)d_in[14];
    const float* global_bias  = (const float*)d_in[15];
    float* out = (float*)d_out;

    proj_kernel<<<VOCAB / TVP + 1, 160>>>(emb_table, conv_w, fc_w2_w);
    review_kernel<<<2 * NREV, 256>>>(user_reviews, item_reviews,
                                     conv_b, fc_w_w, fc_w_b,
                                     fc_w2_b, h_r_w, h_c_w, out);
    qsum_kernel<<<(50 * 512 + 255) / 256, 256>>>();
    pair_kernel<<<dim3(N_NODE, 2), 256>>>();
    edge_kernel<<<(Ee + 255) / 256, 256>>>(uid, iid, user_bias, item_bias, global_bias, out);
}

// round 5
// speedup vs baseline: 2.4964x; 1.0934x over previous
#include <cuda_runtime.h>
#include <math.h>

// ---------------- constants ----------------
#define VOCAB 20000
#define Dd 100
#define Hh 100
#define N_NODE 256
#define Rr 8
#define Ss 52
#define SP 50
#define Ee 20000
#define NREV 2048

typedef unsigned long long u64;

__device__ __forceinline__ void ffma2(u64 &c, u64 a, u64 b) {
    asm("fma.rn.f32x2 %0, %1, %2, %0;" : "+l"(c) : "l"(a), "l"(b));
}
__device__ __forceinline__ float2 f2u(u64 v) {
    float2 r; asm("mov.b64 {%0, %1}, %2;" : "=f"(r.x), "=f"(r.y) : "l"(v)); return r;
}

union V4 { float4 f; u64 u[2]; };

// ---------------- device scratch ----------------
__device__ __align__(16) float g_proj[VOCAB * 300];     // [v][k*100+h]
__device__ __align__(16) float4 g_wt4[25 * 300];        // [j][n]: (w[4j..4j+3][n])
__device__ __align__(16) float g_w2t[Hh * Dd];          // [h][d]
__device__ __align__(16) float g_P[2 * NREV * Dd];
__device__ __align__(16) float g_Qt[50 * 512 * 2];      // [d2][n] float2 pairs
__device__ __align__(16) float g_zw[2 * NREV];
__device__ __align__(16) float g_pc[2 * NREV];
__device__ __align__(16) float g_A[N_NODE * N_NODE * Rr];
__device__ __align__(16) float g_B[N_NODE * N_NODE * Rr];

// ---------------- K0: transpose conv_w -> wt4, fc_w2_w -> w2t ----------------
__global__ void transpose_kernel(const float* __restrict__ convw, const float* __restrict__ w2)
{
    const int idx = blockIdx.x * 256 + threadIdx.x;
    if (idx < 7500) {
        const int j = idx / 300, n = idx - j * 300;
        const int h = n % 100, k = n / 100;
        const float* s = convw + h * 300 + k * 100 + 4 * j;
        g_wt4[idx] = make_float4(s[0], s[1], s[2], s[3]);
    } else if (idx < 17500) {
        const int i = idx - 7500;           // i = d*100 + h
        const int d = i / 100, h = i - d * 100;
        g_w2t[h * 100 + d] = w2[i];
    }
}

// ---------------- K1: proj via f32x2, coalesced wt4 weights ----------------
#define TVP 8
__global__ void proj_kernel(const float* __restrict__ emb)
{
    __shared__ __align__(16) float4 esh[TVP][25];
    const int v0 = blockIdx.x * TVP;
    const int tid = threadIdx.x;

    for (int i = tid; i < TVP * 25; i += 160) {
        int v = i / 25, d4 = i % 25;
        esh[v][d4] = reinterpret_cast<const float4*>(emb)[(v0 + v) * 25 + d4];
    }
    __syncthreads();
    if (tid >= 150) return;

    const int n0 = tid, n1 = tid + 150;

    u64 acc0[TVP], acc1[TVP];
#pragma unroll
    for (int v = 0; v < TVP; v++) { acc0[v] = 0ull; acc1[v] = 0ull; }

#pragma unroll 5
    for (int j = 0; j < 25; j++) {
        V4 w0, w1;
        w0.f = __ldg(reinterpret_cast<const float4*>(g_wt4) + j * 300 + n0);  // coalesced
        w1.f = __ldg(reinterpret_cast<const float4*>(g_wt4) + j * 300 + n1);
#pragma unroll
        for (int v = 0; v < TVP; v++) {
            V4 e; e.f = esh[v][j];
            ffma2(acc0[v], e.u[0], w0.u[0]);
            ffma2(acc0[v], e.u[1], w0.u[1]);
            ffma2(acc1[v], e.u[0], w1.u[0]);
            ffma2(acc1[v], e.u[1], w1.u[1]);
        }
    }
#pragma unroll
    for (int v = 0; v < TVP; v++) {
        float2 a0 = f2u(acc0[v]), a1 = f2u(acc1[v]);
        g_proj[(v0 + v) * 300 + n0] = a0.x + a0.y;
        g_proj[(v0 + v) * 300 + n1] = a1.x + a1.y;
    }
}

// ---------------- K2: per-review fused kernel ----------------
__global__ void review_kernel(const int* __restrict__ ur, const int* __restrict__ ir,
                              const float* __restrict__ convb,
                              const float* __restrict__ fcw, const float* __restrict__ fcb,
                              const float* __restrict__ w2b,
                              const float* __restrict__ hrw, const float* __restrict__ hcw,
                              float* __restrict__ out)
{
    __shared__ __align__(16) float c_sh[SP * 104];
    __shared__ __align__(16) float cb[Hh], fw[Hh];
    __shared__ float zsh[SP], cmax[Hh], Psh[Hh];
    __shared__ int tok[Ss];

    const int bid = blockIdx.x;
    const int br  = bid >> 11;
    const int idx = bid & 2047;
    const int tid = threadIdx.x;
    const int* revs = br ? ir : ur;

    if (tid < Ss)  tok[tid] = revs[idx * Ss + tid];
    if (tid >= 64 && tid < 64 + Hh) { int h = tid - 64; cb[h] = convb[h]; fw[h] = fcw[h]; }
    __syncthreads();

    for (int i = tid; i < SP * 25; i += 256) {
        const int s = i / 25, h4 = i - s * 25;
        const float4 a = __ldg(reinterpret_cast<const float4*>(g_proj + tok[s]     * 300      ) + h4);
        const float4 b = __ldg(reinterpret_cast<const float4*>(g_proj + tok[s + 1] * 300 + 100) + h4);
        const float4 c = __ldg(reinterpret_cast<const float4*>(g_proj + tok[s + 2] * 300 + 200) + h4);
        const float4 bb = reinterpret_cast<const float4*>(cb)[h4];
        float4 v;
        v.x = fmaxf(bb.x + a.x + b.x + c.x, 0.f);
        v.y = fmaxf(bb.y + a.y + b.y + c.y, 0.f);
        v.z = fmaxf(bb.z + a.z + b.z + c.z, 0.f);
        v.w = fmaxf(bb.w + a.w + b.w + c.w, 0.f);
        reinterpret_cast<float4*>(c_sh + s * 104)[h4] = v;
    }
    __syncthreads();

    if (tid < SP) {
        const float4* crow = reinterpret_cast<const float4*>(c_sh + tid * 104);
        float x = fcb[0];
#pragma unroll 5
        for (int j = 0; j < 25; j++) {
            float4 v = crow[j];
            float4 w = reinterpret_cast<const float4*>(fw)[j];
            x += v.x * w.x + v.y * w.y + v.z * w.z + v.w * w.w;
        }
        float rho = 1.f / (1.f + expf(-x));
        float z = rintf(rho);
        zsh[tid] = z;
        out[2 * Ee + bid * SP + tid] = z;
    }
    if (tid >= 64 && tid < 64 + Hh) {
        const int h = tid - 64;
        float m = 0.f;
#pragma unroll 5
        for (int s = 0; s < SP; s++) m = fmaxf(m, c_sh[s * 104 + h]);
        cmax[h] = m;
    }
    __syncthreads();

    if (tid < Dd) {
        float p = w2b[tid];
#pragma unroll 4
        for (int h = 0; h < Hh; h++) p += cmax[h] * g_w2t[h * Dd + tid];
        Psh[tid] = p;
        g_P[bid * Dd + tid] = p;
    }
    if (tid >= 192 && tid < 224) {
        const int l = tid - 192;
        float a = (l < SP) ? zsh[l] * hrw[br * SP + l] : 0.f;
        if (l + 32 < SP) a += zsh[l + 32] * hrw[br * SP + l + 32];
#pragma unroll
        for (int o = 16; o > 0; o >>= 1) a += __shfl_xor_sync(0xffffffffu, a, o);
        if (l == 0) g_zw[bid] = a;
    }
    __syncthreads();

    if (tid < 32) {
        float a = 0.f;
#pragma unroll
        for (int j = 0; j < 4; j++) {
            int d = tid + 32 * j;
            if (d < Dd) a += Psh[d] * hcw[br * Dd + d];
        }
#pragma unroll
        for (int o = 16; o > 0; o >>= 1) a += __shfl_xor_sync(0xffffffffu, a, o);
        if (tid == 0) g_pc[bid] = a;
    }
}

// ---------------- K3: Qt2[d2][n] = sum_r P[n,r,(2d2,2d2+1)] ----------------
__global__ void qsum_kernel()
{
    const int idx = blockIdx.x * 256 + threadIdx.x;
    if (idx >= 50 * 512) return;
    const int d2 = idx >> 9;
    const int n  = idx & 511;
    float qx = 0.f, qy = 0.f;
    const float* base = g_P + n * (Rr * Dd) + 2 * d2;
#pragma unroll
    for (int r = 0; r < Rr; r++) {
        float2 p = *reinterpret_cast<const float2*>(base + r * Dd);
        qx += p.x; qy += p.y;
    }
    reinterpret_cast<float2*>(g_Qt)[idx] = make_float2(qx, qy);
}

// ---------------- K4: pair scores — pipelined q loads + LDS.128 P ----------------
__global__ void __launch_bounds__(256) pair_kernel()
{
    __shared__ __align__(16) float Pt[50 * 16];

    const int pb  = blockIdx.y;
    const int a   = blockIdx.x;
    const int tid = threadIdx.x;

    const float* Pbase = g_P + (pb * NREV + a * Rr) * Dd;
    for (int i = tid; i < Rr * Dd; i += 256) {
        int r = i / Dd, d = i - r * Dd;
        Pt[(d >> 1) * 16 + r * 2 + (d & 1)] = Pbase[i];
    }
    __syncthreads();

    const int off = (1 - pb) * N_NODE;
    const u64* qcol = reinterpret_cast<const u64*>(g_Qt) + off + tid;

    u64 acc[Rr];
#pragma unroll
    for (int r = 0; r < Rr; r++) acc[r] = 0ull;

    // depth-2 software pipeline, chunks of 5 q loads
    u64 q[2][5];
#pragma unroll
    for (int t = 0; t < 5; t++) q[0][t] = __ldg(qcol + t * 512);

#pragma unroll
    for (int c = 0; c < 10; c++) {
        const int cur = c & 1, nxt = cur ^ 1;
        if (c < 9) {
#pragma unroll
            for (int t = 0; t < 5; t++) q[nxt][t] = __ldg(qcol + ((c + 1) * 5 + t) * 512);
        }
#pragma unroll
        for (int t = 0; t < 5; t++) {
            const int d2 = c * 5 + t;
            const float4* row = reinterpret_cast<const float4*>(Pt + d2 * 16);
            V4 p0, p1, p2, p3;
            p0.f = row[0]; p1.f = row[1]; p2.f = row[2]; p3.f = row[3];
            u64 qq = q[cur][t];
            ffma2(acc[0], qq, p0.u[0]);
            ffma2(acc[1], qq, p0.u[1]);
            ffma2(acc[2], qq, p1.u[0]);
            ffma2(acc[3], qq, p1.u[1]);
            ffma2(acc[4], qq, p2.u[0]);
            ffma2(acc[5], qq, p2.u[1]);
            ffma2(acc[6], qq, p3.u[0]);
            ffma2(acc[7], qq, p3.u[1]);
        }
    }

    float v[Rr];
#pragma unroll
    for (int r = 0; r < Rr; r++) { float2 t = f2u(acc[r]); v[r] = t.x + t.y; }
    float* dst = (pb ? g_B : g_A) + (a * N_NODE + tid) * Rr;
    reinterpret_cast<float4*>(dst)[0] = make_float4(v[0], v[1], v[2], v[3]);
    reinterpret_cast<float4*>(dst)[1] = make_float4(v[4], v[5], v[6], v[7]);
}

// ---------------- K5: per-edge predictions ----------------
__global__ void edge_kernel(const int* __restrict__ uid, const int* __restrict__ iid,
                            const float* __restrict__ ubias, const float* __restrict__ ibias,
                            const float* __restrict__ gbias, float* __restrict__ out)
{
    const int e = blockIdx.x * 256 + threadIdx.x;
    if (e >= Ee) return;
    const int u = uid[e], i = iid[e];

    const float4* A4 = reinterpret_cast<const float4*>(g_A + (u * N_NODE + i) * Rr);
    const float4* B4 = reinterpret_cast<const float4*>(g_B + (i * N_NODE + u) * Rr);
    float Av[Rr], Bv[Rr];
    *reinterpret_cast<float4*>(Av)     = A4[0];
    *reinterpret_cast<float4*>(Av + 4) = A4[1];
    *reinterpret_cast<float4*>(Bv)     = B4[0];
    *reinterpret_cast<float4*>(Bv + 4) = B4[1];

    const float* zwu = g_zw + u * Rr;
    const float* zwi = g_zw + NREV + i * Rr;
    const float* pcu = g_pc + u * Rr;
    const float* pci = g_pc + NREV + i * Rr;

    float pr = ubias[u] + ibias[i] + gbias[0];
    float pc = 0.f;
#pragma unroll
    for (int r = 0; r < Rr; r++) {
        float su = 1.f / (1.f + expf(-Av[r]));
        float sv = 1.f / (1.f + expf(-Bv[r]));
        pr += su * zwu[r] + sv * zwi[r];
        pc += su * pcu[r] + sv * pci[r];
    }
    out[e]      = pr;
    out[Ee + e] = pc;
}

// ---------------- launcher ----------------
extern "C" void kernel_launch(void* const* d_in, const int* in_sizes, int n_in,
                              void* d_out, int out_size)
{
    const int*   user_reviews = (const int*)  d_in[0];
    const int*   item_reviews = (const int*)  d_in[1];
    const int*   uid          = (const int*)  d_in[2];
    const int*   iid          = (const int*)  d_in[3];
    const float* emb_table    = (const float*)d_in[4];
    const float* conv_w       = (const float*)d_in[5];
    const float* conv_b       = (const float*)d_in[6];
    const float* fc_w_w       = (const float*)d_in[7];
    const float* fc_w_b       = (const float*)d_in[8];
    const float* fc_w2_w      = (const float*)d_in[9];
    const float* fc_w2_b      = (const float*)d_in[10];
    const float* h_r_w        = (const float*)d_in[11];
    const float* h_c_w        = (const float*)d_in[12];
    const float* user_bias    = (const float*)d_in[13];
    const float* item_bias    = (const float*)d_in[14];
    const float* global_bias  = (const float*)d_in[15];
    float* out = (float*)d_out;

    transpose_kernel<<<69, 256>>>(conv_w, fc_w2_w);
    proj_kernel<<<VOCAB / TVP, 160>>>(emb_table);
    review_kernel<<<2 * NREV, 256>>>(user_reviews, item_reviews,
                                     conv_b, fc_w_w, fc_w_b,
                                     fc_w2_b, h_r_w, h_c_w, out);
    qsum_kernel<<<(50 * 512 + 255) / 256, 256>>>();
    pair_kernel<<<dim3(N_NODE, 2), 256>>>();
    edge_kernel<<<(Ee + 255) / 256, 256>>>(uid, iid, user_bias, item_bias, global_bias, out);
}

// round 6
// speedup vs baseline: 2.7152x; 1.0877x over previous
#include <cuda_runtime.h>
#include <math.h>

// ---------------- constants ----------------
#define VOCAB 20000
#define Dd 100
#define Hh 100
#define N_NODE 256
#define Rr 8
#define Ss 52
#define SP 50
#define Ee 20000
#define NREV 2048

typedef unsigned long long u64;

__device__ __forceinline__ void ffma2(u64 &c, u64 a, u64 b) {
    asm("fma.rn.f32x2 %0, %1, %2, %0;" : "+l"(c) : "l"(a), "l"(b));
}
__device__ __forceinline__ float2 f2u(u64 v) {
    float2 r; asm("mov.b64 {%0, %1}, %2;" : "=f"(r.x), "=f"(r.y) : "l"(v)); return r;
}

union V4 { float4 f; u64 u[2]; };

// ---------------- device scratch ----------------
__device__ __align__(16) float g_proj[VOCAB * 300];     // [v][k*100+h]
__device__ __align__(16) float4 g_wt4[25 * 300];        // [j][n]
__device__ __align__(16) float g_w2t[Hh * Dd];          // [h][d]
__device__ __align__(16) float g_cmax[2 * NREV * Hh];   // [row][h]
__device__ __align__(16) float g_P[2 * NREV * Dd];      // [row][d]
__device__ __align__(16) float g_Qt[50 * 512 * 2];      // [d2][n] float2
__device__ __align__(16) float g_zw[2 * NREV];
__device__ __align__(16) float g_pc[2 * NREV];
__device__ __align__(16) float g_A[N_NODE * N_NODE * Rr];
__device__ __align__(16) float g_B[N_NODE * N_NODE * Rr];

// ---------------- K1: proj via f32x2 + transpose tail blocks ----------------
#define TVP 8
#define PROJ_BLOCKS (VOCAB / TVP)
__global__ void proj_kernel(const float* __restrict__ emb, const float* __restrict__ convw,
                            const float* __restrict__ w2)
{
    const int tid = threadIdx.x;
    if (blockIdx.x >= PROJ_BLOCKS) {
        // transpose tail: conv_w -> wt4, fc_w2_w -> w2t
        const int t = (blockIdx.x - PROJ_BLOCKS) * 160 + tid;
        if (t < 7500) {
            const int j = t / 300, n = t - j * 300;
            const int h = n % 100, k = n / 100;
            const float* s = convw + h * 300 + k * 100 + 4 * j;
            g_wt4[t] = make_float4(s[0], s[1], s[2], s[3]);
        } else if (t < 17500) {
            const int i = t - 7500;              // i = d*100 + h
            const int d = i / 100, h = i - d * 100;
            g_w2t[h * 100 + d] = w2[i];
        }
        return;
    }

    __shared__ __align__(16) float4 esh[TVP][25];
    const int v0 = blockIdx.x * TVP;

    for (int i = tid; i < TVP * 25; i += 160) {
        int v = i / 25, d4 = i % 25;
        esh[v][d4] = reinterpret_cast<const float4*>(emb)[(v0 + v) * 25 + d4];
    }
    __syncthreads();
    if (tid >= 150) return;

    const int n0 = tid, n1 = tid + 150;

    u64 acc0[TVP], acc1[TVP];
#pragma unroll
    for (int v = 0; v < TVP; v++) { acc0[v] = 0ull; acc1[v] = 0ull; }

#pragma unroll 5
    for (int j = 0; j < 25; j++) {
        V4 w0, w1;
        w0.f = __ldg(reinterpret_cast<const float4*>(g_wt4) + j * 300 + n0);
        w1.f = __ldg(reinterpret_cast<const float4*>(g_wt4) + j * 300 + n1);
#pragma unroll
        for (int v = 0; v < TVP; v++) {
            V4 e; e.f = esh[v][j];
            ffma2(acc0[v], e.u[0], w0.u[0]);
            ffma2(acc0[v], e.u[1], w0.u[1]);
            ffma2(acc1[v], e.u[0], w1.u[0]);
            ffma2(acc1[v], e.u[1], w1.u[1]);
        }
    }
#pragma unroll
    for (int v = 0; v < TVP; v++) {
        float2 a0 = f2u(acc0[v]), a1 = f2u(acc1[v]);
        g_proj[(v0 + v) * 300 + n0] = a0.x + a0.y;
        g_proj[(v0 + v) * 300 + n1] = a1.x + a1.y;
    }
}

// K1b: wait-free split — transpose must complete before proj reads g_wt4.
// Separate tiny kernel launched BEFORE proj (dependency via stream order).
__global__ void transpose_kernel(const float* __restrict__ convw, const float* __restrict__ w2)
{
    const int t = blockIdx.x * 256 + threadIdx.x;
    if (t < 7500) {
        const int j = t / 300, n = t - j * 300;
        const int h = n % 100, k = n / 100;
        const float* s = convw + h * 300 + k * 100 + 4 * j;
        g_wt4[t] = make_float4(s[0], s[1], s[2], s[3]);
    } else if (t < 17500) {
        const int i = t - 7500;
        const int d = i / 100, h = i - d * 100;
        g_w2t[h * 100 + d] = w2[i];
    }
}

// ---------------- K2: per-review: conv + z + cmax + zw ----------------
__global__ void review_kernel(const int* __restrict__ ur, const int* __restrict__ ir,
                              const float* __restrict__ convb,
                              const float* __restrict__ fcw, const float* __restrict__ fcb,
                              const float* __restrict__ hrw,
                              float* __restrict__ out)
{
    __shared__ __align__(16) float c_sh[SP * 104];
    __shared__ __align__(16) float cb[Hh], fw[Hh];
    __shared__ float zsh[SP];
    __shared__ int tok[Ss];

    const int bid = blockIdx.x;
    const int br  = bid >> 11;
    const int idx = bid & 2047;
    const int tid = threadIdx.x;
    const int* revs = br ? ir : ur;

    if (tid < Ss)  tok[tid] = revs[idx * Ss + tid];
    if (tid >= 64 && tid < 64 + Hh) { int h = tid - 64; cb[h] = convb[h]; fw[h] = fcw[h]; }
    __syncthreads();

    for (int i = tid; i < SP * 25; i += 256) {
        const int s = i / 25, h4 = i - s * 25;
        const float4 a = __ldg(reinterpret_cast<const float4*>(g_proj + tok[s]     * 300      ) + h4);
        const float4 b = __ldg(reinterpret_cast<const float4*>(g_proj + tok[s + 1] * 300 + 100) + h4);
        const float4 c = __ldg(reinterpret_cast<const float4*>(g_proj + tok[s + 2] * 300 + 200) + h4);
        const float4 bb = reinterpret_cast<const float4*>(cb)[h4];
        float4 v;
        v.x = fmaxf(bb.x + a.x + b.x + c.x, 0.f);
        v.y = fmaxf(bb.y + a.y + b.y + c.y, 0.f);
        v.z = fmaxf(bb.z + a.z + b.z + c.z, 0.f);
        v.w = fmaxf(bb.w + a.w + b.w + c.w, 0.f);
        reinterpret_cast<float4*>(c_sh + s * 104)[h4] = v;
    }
    __syncthreads();

    // rho -> z on warps 0-1
    if (tid < SP) {
        const float4* crow = reinterpret_cast<const float4*>(c_sh + tid * 104);
        float x = fcb[0];
#pragma unroll 5
        for (int j = 0; j < 25; j++) {
            float4 v = crow[j];
            float4 w = reinterpret_cast<const float4*>(fw)[j];
            x += v.x * w.x + v.y * w.y + v.z * w.z + v.w * w.w;
        }
        float rho = 1.f / (1.f + expf(-x));
        float z = rintf(rho);
        zsh[tid] = z;
        out[2 * Ee + bid * SP + tid] = z;
    }
    // cmax on warps 2-5 -> straight to global
    if (tid >= 64 && tid < 64 + Hh) {
        const int h = tid - 64;
        float m = 0.f;
#pragma unroll 5
        for (int s = 0; s < SP; s++) m = fmaxf(m, c_sh[s * 104 + h]);
        g_cmax[bid * Hh + h] = m;
    }
    __syncthreads();

    // zw reduction on warp 6
    if (tid >= 192 && tid < 224) {
        const int l = tid - 192;
        float a = (l < SP) ? zsh[l] * hrw[br * SP + l] : 0.f;
        if (l + 32 < SP) a += zsh[l + 32] * hrw[br * SP + l + 32];
#pragma unroll
        for (int o = 16; o > 0; o >>= 1) a += __shfl_xor_sync(0xffffffffu, a, o);
        if (l == 0) g_zw[bid] = a;
    }
}

// ---------------- K3: P = cmax @ w2t + b (16 rows/block) + Qt epilogue ----------------
// grid 256, block 200: c = tid%100, half = tid/100 (rows half*8..half*8+7 = one node)
__global__ void pgemm_kernel(const float* __restrict__ w2b)
{
    __shared__ float w2s[Hh * Dd];       // 40KB
    __shared__ float cms[16 * Hh];       // 6.4KB

    const int tid  = threadIdx.x;
    const int base = blockIdx.x * 16;

    for (int i = tid; i < Hh * Dd; i += 200) w2s[i] = g_w2t[i];
    for (int i = tid; i < 16 * Hh; i += 200) cms[i] = g_cmax[base * Hh + i];
    __syncthreads();

    const int c = tid % 100, half = tid / 100;
    float acc[8];
    const float bias = w2b[c];
#pragma unroll
    for (int j = 0; j < 8; j++) acc[j] = bias;

#pragma unroll 4
    for (int h = 0; h < Hh; h++) {
        const float wv = w2s[h * 100 + c];
#pragma unroll
        for (int j = 0; j < 8; j++)
            acc[j] += cms[(half * 8 + j) * Hh + h] * wv;
    }

    float q = 0.f;
#pragma unroll
    for (int j = 0; j < 8; j++) {
        g_P[(base + half * 8 + j) * Dd + c] = acc[j];
        q += acc[j];
    }
    const int n = blockIdx.x * 2 + half;          // node index (0..511)
    g_Qt[(c >> 1) * 1024 + n * 2 + (c & 1)] = q;
}

// ---------------- K3b: pc[row] = P[row,:] . hcw (warp per row) ----------------
__global__ void pc_kernel(const float* __restrict__ hcw)
{
    const int row  = blockIdx.x * 8 + (threadIdx.x >> 5);
    const int lane = threadIdx.x & 31;
    const int br   = row >> 11;
    const float* p = g_P + row * Dd;
    float a = 0.f;
#pragma unroll
    for (int j = 0; j < 4; j++) {
        int d = lane + 32 * j;
        if (d < Dd) a += p[d] * hcw[br * Dd + d];
    }
#pragma unroll
    for (int o = 16; o > 0; o >>= 1) a += __shfl_xor_sync(0xffffffffu, a, o);
    if (lane == 0) g_pc[row] = a;
}

// ---------------- K4: pair scores — pipelined q loads + LDS.128 P ----------------
__global__ void __launch_bounds__(256) pair_kernel()
{
    __shared__ __align__(16) float Pt[50 * 16];

    const int pb  = blockIdx.y;
    const int a   = blockIdx.x;
    const int tid = threadIdx.x;

    const float* Pbase = g_P + (pb * NREV + a * Rr) * Dd;
    for (int i = tid; i < Rr * Dd; i += 256) {
        int r = i / Dd, d = i - r * Dd;
        Pt[(d >> 1) * 16 + r * 2 + (d & 1)] = Pbase[i];
    }
    __syncthreads();

    const int off = (1 - pb) * N_NODE;
    const u64* qcol = reinterpret_cast<const u64*>(g_Qt) + off + tid;

    u64 acc[Rr];
#pragma unroll
    for (int r = 0; r < Rr; r++) acc[r] = 0ull;

    u64 q[2][5];
#pragma unroll
    for (int t = 0; t < 5; t++) q[0][t] = __ldg(qcol + t * 512);

#pragma unroll
    for (int c = 0; c < 10; c++) {
        const int cur = c & 1, nxt = cur ^ 1;
        if (c < 9) {
#pragma unroll
            for (int t = 0; t < 5; t++) q[nxt][t] = __ldg(qcol + ((c + 1) * 5 + t) * 512);
        }
#pragma unroll
        for (int t = 0; t < 5; t++) {
            const int d2 = c * 5 + t;
            const float4* row = reinterpret_cast<const float4*>(Pt + d2 * 16);
            V4 p0, p1, p2, p3;
            p0.f = row[0]; p1.f = row[1]; p2.f = row[2]; p3.f = row[3];
            u64 qq = q[cur][t];
            ffma2(acc[0], qq, p0.u[0]);
            ffma2(acc[1], qq, p0.u[1]);
            ffma2(acc[2], qq, p1.u[0]);
            ffma2(acc[3], qq, p1.u[1]);
            ffma2(acc[4], qq, p2.u[0]);
            ffma2(acc[5], qq, p2.u[1]);
            ffma2(acc[6], qq, p3.u[0]);
            ffma2(acc[7], qq, p3.u[1]);
        }
    }

    float v[Rr];
#pragma unroll
    for (int r = 0; r < Rr; r++) { float2 t = f2u(acc[r]); v[r] = t.x + t.y; }
    float* dst = (pb ? g_B : g_A) + (a * N_NODE + tid) * Rr;
    reinterpret_cast<float4*>(dst)[0] = make_float4(v[0], v[1], v[2], v[3]);
    reinterpret_cast<float4*>(dst)[1] = make_float4(v[4], v[5], v[6], v[7]);
}

// ---------------- K5: per-edge predictions ----------------
__global__ void edge_kernel(const int* __restrict__ uid, const int* __restrict__ iid,
                            const float* __restrict__ ubias, const float* __restrict__ ibias,
                            const float* __restrict__ gbias, float* __restrict__ out)
{
    const int e = blockIdx.x * 256 + threadIdx.x;
    if (e >= Ee) return;
    const int u = uid[e], i = iid[e];

    const float4* A4 = reinterpret_cast<const float4*>(g_A + (u * N_NODE + i) * Rr);
    const float4* B4 = reinterpret_cast<const float4*>(g_B + (i * N_NODE + u) * Rr);
    float Av[Rr], Bv[Rr];
    *reinterpret_cast<float4*>(Av)     = A4[0];
    *reinterpret_cast<float4*>(Av + 4) = A4[1];
    *reinterpret_cast<float4*>(Bv)     = B4[0];
    *reinterpret_cast<float4*>(Bv + 4) = B4[1];

    const float* zwu = g_zw + u * Rr;
    const float* zwi = g_zw + NREV + i * Rr;
    const float* pcu = g_pc + u * Rr;
    const float* pci = g_pc + NREV + i * Rr;

    float pr = ubias[u] + ibias[i] + gbias[0];
    float pc = 0.f;
#pragma unroll
    for (int r = 0; r < Rr; r++) {
        float su = 1.f / (1.f + expf(-Av[r]));
        float sv = 1.f / (1.f + expf(-Bv[r]));
        pr += su * zwu[r] + sv * zwi[r];
        pc += su * pcu[r] + sv * pci[r];
    }
    out[e]      = pr;
    out[Ee + e] = pc;
}

// ---------------- launcher ----------------
extern "C" void kernel_launch(void* const* d_in, const int* in_sizes, int n_in,
                              void* d_out, int out_size)
{
    const int*   user_reviews = (const int*)  d_in[0];
    const int*   item_reviews = (const int*)  d_in[1];
    const int*   uid          = (const int*)  d_in[2];
    const int*   iid          = (const int*)  d_in[3];
    const float* emb_table    = (const float*)d_in[4];
    const float* conv_w       = (const float*)d_in[5];
    const float* conv_b       = (const float*)d_in[6];
    const float* fc_w_w       = (const float*)d_in[7];
    const float* fc_w_b       = (const float*)d_in[8];
    const float* fc_w2_w      = (const float*)d_in[9];
    const float* fc_w2_b      = (const float*)d_in[10];
    const float* h_r_w        = (const float*)d_in[11];
    const float* h_c_w        = (const float*)d_in[12];
    const float* user_bias    = (const float*)d_in[13];
    const float* item_bias    = (const float*)d_in[14];
    const float* global_bias  = (const float*)d_in[15];
    float* out = (float*)d_out;

    transpose_kernel<<<69, 256>>>(conv_w, fc_w2_w);
    proj_kernel<<<PROJ_BLOCKS, 160>>>(emb_table, conv_w, fc_w2_w);
    review_kernel<<<2 * NREV, 256>>>(user_reviews, item_reviews,
                                     conv_b, fc_w_w, fc_w_b, h_r_w, out);
    pgemm_kernel<<<256, 200>>>(fc_w2_b);
    pc_kernel<<<2 * NREV / 8, 256>>>(h_c_w);
    pair_kernel<<<dim3(N_NODE, 2), 256>>>();
    edge_kernel<<<(Ee + 255) / 256, 256>>>(uid, iid, user_bias, item_bias, global_bias, out);
}